// round 11
// baseline (speedup 1.0000x reference)
#include <cuda_runtime.h>
#include <cuda_bf16.h>
#include <cstdint>
#include <math.h>

// Problem constants
#define S_STEPS 2048   // T*P
#define NB      64     // batch
#define NI      256    // input
#define NH      128    // hidden
#define NG      512    // 4*H
#define NO      88     // output
#define MTOT    (S_STEPS * NB)   // 131072 GEMM rows

// Scratch (static __device__ — allocation APIs are forbidden)
__device__ float g_proj[(size_t)2 * S_STEPS * NB * NG];          // 512 MB
__device__ float g_tout[(size_t)S_STEPS * NB * 256];             // 128 MB
__device__ float g_pout[NB * 256];
__device__ __nv_bfloat16 g_Ah[(size_t)MTOT * 256];               // 64 MB
__device__ __nv_bfloat16 g_Al[(size_t)MTOT * 256];               // 64 MB
__device__ __nv_bfloat16 g_Bh[1024 * 256];
__device__ __nv_bfloat16 g_Bl[1024 * 256];
__device__ float g_bias[1024];

// ---------------- helpers ----------------
__device__ __forceinline__ uint32_t smem_u32(const void* p) {
    uint32_t a;
    asm("{ .reg .u64 t; cvta.to.shared.u64 t, %1; cvt.u32.u64 %0, t; }" : "=r"(a) : "l"(p));
    return a;
}
__device__ __forceinline__ uint32_t mapa_rank(uint32_t a, uint32_t rk) {
    uint32_t r;
    asm("mapa.shared::cluster.u32 %0, %1, %2;" : "=r"(r) : "r"(a), "r"(rk));
    return r;
}
__device__ __forceinline__ void st_cluster_f32(uint32_t a, float v) {
    asm volatile("st.shared::cluster.f32 [%0], %1;" :: "r"(a), "f"(v) : "memory");
}
__device__ __forceinline__ void cluster_sync_() {
    asm volatile("barrier.cluster.arrive.aligned;" ::: "memory");
    asm volatile("barrier.cluster.wait.aligned;" ::: "memory");
}
__device__ __forceinline__ unsigned long long ffma2(unsigned long long a, unsigned long long b,
                                                    unsigned long long c) {
    unsigned long long d;
    asm("fma.rn.f32x2 %0, %1, %2, %3;" : "=l"(d) : "l"(a), "l"(b), "l"(c));
    return d;
}
__device__ __forceinline__ float2 unpk64(unsigned long long v) {
    float2 f;
    asm("mov.b64 {%0, %1}, %2;" : "=f"(f.x), "=f"(f.y) : "l"(v));
    return f;
}
__device__ __forceinline__ float fsig(float x) {
    float e, r;
    asm("ex2.approx.ftz.f32 %0, %1;" : "=f"(e) : "f"(-1.4426950408889634f * x));
    asm("rcp.approx.ftz.f32 %0, %1;" : "=f"(r) : "f"(1.0f + e));
    return r;
}
__device__ __forceinline__ float ftanh_(float x) {
    float e, r;
    asm("ex2.approx.ftz.f32 %0, %1;" : "=f"(e) : "f"(2.8853900817779268f * x));
    asm("rcp.approx.ftz.f32 %0, %1;" : "=f"(r) : "f"(1.0f + e));
    return fmaf(-2.0f, r, 1.0f);   // tanh(x) = 1 - 2/(1+e^{2x})
}
__device__ __forceinline__ void mma16816(float* c, const uint32_t* a, const uint32_t* b) {
    asm volatile(
        "mma.sync.aligned.m16n8k16.row.col.f32.bf16.bf16.f32 "
        "{%0,%1,%2,%3}, {%4,%5,%6,%7}, {%8,%9}, {%0,%1,%2,%3};"
        : "+f"(c[0]), "+f"(c[1]), "+f"(c[2]), "+f"(c[3])
        : "r"(a[0]), "r"(a[1]), "r"(a[2]), "r"(a[3]), "r"(b[0]), "r"(b[1]));
}

// ---------------- conversion: fp32 A (strided) -> bf16 hi/lo [m][k] ----------------
__global__ void __launch_bounds__(256)
conv_a_kernel(const float* __restrict__ Aext, long long sbB, long long sbS, int internal)
{
    const float* A = internal ? (const float*)g_tout : Aext;
    size_t idx = ((size_t)blockIdx.x * 256 + threadIdx.x) * 8;
    int m = (int)(idx >> 8), k = (int)(idx & 255);
    const float* src = A + (size_t)(m & 63) * sbB + (size_t)(m >> 6) * sbS + k;
    float4 v0 = *(const float4*)src;
    float4 v1 = *(const float4*)(src + 4);
    float f[8] = {v0.x, v0.y, v0.z, v0.w, v1.x, v1.y, v1.z, v1.w};
    union { __nv_bfloat16 b[8]; uint4 u; } hi, lo;
    #pragma unroll
    for (int i = 0; i < 8; i++) {
        hi.b[i] = __float2bfloat16(f[i]);
        lo.b[i] = __float2bfloat16(f[i] - __bfloat162float(hi.b[i]));
    }
    *(uint4*)&g_Ah[idx] = hi.u;
    *(uint4*)&g_Al[idx] = lo.u;
}

// ---------------- conversion: W -> permuted bf16 hi/lo + fused bias ----------------
__global__ void __launch_bounds__(256)
conv_w_kernel(const float* __restrict__ W, const float* __restrict__ bia,
              const float* __restrict__ bib)
{
    size_t idx = ((size_t)blockIdx.x * 256 + threadIdx.x) * 8;
    int n = (int)(idx >> 8), k = (int)(idx & 255);
    int p = n & 511, d = n >> 9;
    int orig = ((p >> 6) & 3) * 128 + ((p >> 8) & 1) * 64 + (p & 63);
    int row = d * 512 + orig;
    const float* src = W + (size_t)row * 256 + k;
    float4 v0 = *(const float4*)src;
    float4 v1 = *(const float4*)(src + 4);
    float f[8] = {v0.x, v0.y, v0.z, v0.w, v1.x, v1.y, v1.z, v1.w};
    union { __nv_bfloat16 b[8]; uint4 u; } hi, lo;
    #pragma unroll
    for (int i = 0; i < 8; i++) {
        hi.b[i] = __float2bfloat16(f[i]);
        lo.b[i] = __float2bfloat16(f[i] - __bfloat162float(hi.b[i]));
    }
    *(uint4*)&g_Bh[idx] = hi.u;
    *(uint4*)&g_Bl[idx] = lo.u;
    if (k == 0) g_bias[n] = bia[row] + bib[row];
}

// ---------------- tensor-core projection GEMM (split-bf16, 3 terms) ----------------
// C[m][n] = sum_k A[m][k]*B[n][k] + bias[n]; out to g_proj[d][s][b][p] (p permuted).
// CTA tile 128x128, K-chunk 32, 8 warps as 4(m) x 2(n), warp tile 32x64.
__global__ void __launch_bounds__(256)
mma_gemm_kernel()
{
    __shared__ __align__(16) __nv_bfloat16 sm[4][128][40];  // Ah, Al, Bh, Bl; stride 40 halves

    const int tid = threadIdx.x;
    const int m0 = blockIdx.y * 128;
    const int n0 = blockIdx.x * 128;
    const int d  = blockIdx.x >> 2;

    const int lane = tid & 31, wid = tid >> 5;
    const int wm = wid >> 1, wn = wid & 1;
    const int fr = lane >> 2, fq = lane & 3;

    float c[2][8][4];
    #pragma unroll
    for (int i = 0; i < 2; i++)
        #pragma unroll
        for (int j = 0; j < 8; j++)
            #pragma unroll
            for (int q = 0; q < 4; q++) c[i][j][q] = 0.0f;

    // gmem load assignment: thread -> (row, 16-element half of the 32-wide chunk)
    // Each thread loads/stores TWO uint4 (16 bf16) per buffer. 256 thr * 16 = 4096 = full tile.
    const int lrow = tid >> 1, lpart = (tid & 1) * 16;
    const __nv_bfloat16* pAh = g_Ah + (size_t)(m0 + lrow) * 256 + lpart;
    const __nv_bfloat16* pAl = g_Al + (size_t)(m0 + lrow) * 256 + lpart;
    const __nv_bfloat16* pBh = g_Bh + (size_t)(n0 + lrow) * 256 + lpart;
    const __nv_bfloat16* pBl = g_Bl + (size_t)(n0 + lrow) * 256 + lpart;

    uint4 ra0 = *(const uint4*)pAh, ra1 = *(const uint4*)(pAh + 8);
    uint4 rb0 = *(const uint4*)pAl, rb1 = *(const uint4*)(pAl + 8);
    uint4 rc0 = *(const uint4*)pBh, rc1 = *(const uint4*)(pBh + 8);
    uint4 rd0 = *(const uint4*)pBl, rd1 = *(const uint4*)(pBl + 8);

    for (int ch = 0; ch < 8; ch++) {
        *(uint4*)&sm[0][lrow][lpart]     = ra0;
        *(uint4*)&sm[0][lrow][lpart + 8] = ra1;
        *(uint4*)&sm[1][lrow][lpart]     = rb0;
        *(uint4*)&sm[1][lrow][lpart + 8] = rb1;
        *(uint4*)&sm[2][lrow][lpart]     = rc0;
        *(uint4*)&sm[2][lrow][lpart + 8] = rc1;
        *(uint4*)&sm[3][lrow][lpart]     = rd0;
        *(uint4*)&sm[3][lrow][lpart + 8] = rd1;
        __syncthreads();
        if (ch < 7) {
            pAh += 32; pAl += 32; pBh += 32; pBl += 32;
            ra0 = *(const uint4*)pAh; ra1 = *(const uint4*)(pAh + 8);
            rb0 = *(const uint4*)pAl; rb1 = *(const uint4*)(pAl + 8);
            rc0 = *(const uint4*)pBh; rc1 = *(const uint4*)(pBh + 8);
            rd0 = *(const uint4*)pBl; rd1 = *(const uint4*)(pBl + 8);
        }
        #pragma unroll
        for (int ks = 0; ks < 32; ks += 16) {
            uint32_t ah[2][4], al[2][4];
            #pragma unroll
            for (int mt = 0; mt < 2; mt++) {
                int rbase = wm * 32 + mt * 16;
                int col = ks + fq * 2;
                ah[mt][0] = *(const uint32_t*)&sm[0][rbase + fr][col];
                ah[mt][1] = *(const uint32_t*)&sm[0][rbase + 8 + fr][col];
                ah[mt][2] = *(const uint32_t*)&sm[0][rbase + fr][col + 8];
                ah[mt][3] = *(const uint32_t*)&sm[0][rbase + 8 + fr][col + 8];
                al[mt][0] = *(const uint32_t*)&sm[1][rbase + fr][col];
                al[mt][1] = *(const uint32_t*)&sm[1][rbase + 8 + fr][col];
                al[mt][2] = *(const uint32_t*)&sm[1][rbase + fr][col + 8];
                al[mt][3] = *(const uint32_t*)&sm[1][rbase + 8 + fr][col + 8];
            }
            #pragma unroll
            for (int nt = 0; nt < 8; nt++) {
                int nr = wn * 64 + nt * 8 + fr;
                int col = ks + fq * 2;
                uint32_t bh[2], bl[2];
                bh[0] = *(const uint32_t*)&sm[2][nr][col];
                bh[1] = *(const uint32_t*)&sm[2][nr][col + 8];
                bl[0] = *(const uint32_t*)&sm[3][nr][col];
                bl[1] = *(const uint32_t*)&sm[3][nr][col + 8];
                #pragma unroll
                for (int mt = 0; mt < 2; mt++) {
                    mma16816(c[mt][nt], ah[mt], bh);   // hi*hi
                    mma16816(c[mt][nt], ah[mt], bl);   // hi*lo
                    mma16816(c[mt][nt], al[mt], bh);   // lo*hi
                }
            }
        }
        __syncthreads();
    }

    // epilogue: bias + permuted-layout store to g_proj
    #pragma unroll
    for (int nt = 0; nt < 8; nt++) {
        int n = n0 + wn * 64 + nt * 8 + fq * 2;
        float b0 = g_bias[n], b1 = g_bias[n + 1];
        int pcol = n & 511;
        #pragma unroll
        for (int mt = 0; mt < 2; mt++) {
            int m1 = m0 + wm * 32 + mt * 16 + fr;
            int m2 = m1 + 8;
            size_t o1 = (((size_t)d * S_STEPS + (m1 >> 6)) * 64 + (m1 & 63)) * 512 + pcol;
            size_t o2 = (((size_t)d * S_STEPS + (m2 >> 6)) * 64 + (m2 & 63)) * 512 + pcol;
            float2 w1 = make_float2(c[mt][nt][0] + b0, c[mt][nt][1] + b1);
            float2 w2 = make_float2(c[mt][nt][2] + b0, c[mt][nt][3] + b1);
            *(float2*)(g_proj + o1) = w1;
            *(float2*)(g_proj + o2) = w2;
        }
    }
}

// ---------------- recurrent scan (FFMA2 matvec + mbarrier cluster handshake) ----------------
// 128 blocks: (dir d, batch-pair bg, half r). Cluster of 2 = the two halves.
// Block r owns gate rows orig = t*128 + r*64 + jj (permuted index p = r*256 + t*64 + jj)
// and updates h/c units j in [r*64, r*64+64). h halves exchanged via DSMEM each step.
__global__ void __launch_bounds__(256, 1) __cluster_dims__(2, 1, 1)
recur_kernel(const float* __restrict__ Whh, int is_time)
{
    __shared__ __align__(16) float hbuf[2][2][128];  // [ping][batch][h]
    __shared__ float gbuf[2][256];
    __shared__ float cbuf[2][64];
    __shared__ __align__(8) unsigned long long mbar;

    const int blk  = blockIdx.x;
    const int r    = blk & 1;
    const int pair = blk >> 1;
    const int d    = pair >> 5;
    const int bg   = pair & 31;
    const int l    = threadIdx.x;          // 0..255 : local gate row
    const int tg   = l >> 6;
    const int jj   = l & 63;
    const int orig = tg * 128 + r * 64 + jj;

    // weights for this gate row -> 64 packed f32x2 registers
    unsigned long long w2[64];
    {
        const unsigned long long* wq =
            (const unsigned long long*)(Whh + ((size_t)d * 512 + orig) * 128);
        #pragma unroll
        for (int i = 0; i < 64; i++) w2[i] = wq[i];
    }

    if (l < 128) {
        hbuf[0][0][l] = 0.f; hbuf[0][1][l] = 0.f;
        hbuf[1][0][l] = 0.f; hbuf[1][1][l] = 0.f;
        cbuf[l >> 6][l & 63] = 0.f;
    }
    if (l == 0) {
        asm volatile("mbarrier.init.shared.b64 [%0], 128;"
                     :: "r"(smem_u32((const void*)&mbar)) : "memory");
    }
    __syncthreads();
    cluster_sync_();   // peer must see our mbarrier init + zeroed hbuf before arriving/writing

    const int b0 = bg * 2;
    const float* pbase = g_proj + (((size_t)d * S_STEPS) * 64 + b0) * 512 + r * 256 + l;
    const long long sstride = 64 * 512;
    float xc0 = pbase[0];
    float xc1 = pbase[512];

    const uint32_t h_local   = smem_u32(&hbuf[0][0][0]);
    const uint32_t h_remote  = mapa_rank(h_local, (uint32_t)(r ^ 1));
    const uint32_t mb_local  = smem_u32((const void*)&mbar);
    const uint32_t mb_remote = mapa_rank(mb_local, (uint32_t)(r ^ 1));

    for (int s = 0; s < S_STEPS; ++s) {
        const int cur = s & 1, nxt = cur ^ 1;
        // packed-f32 matvec: 128 FFMA2 per thread (2 batch elements)
        unsigned long long p00 = 0, p01 = 0, p10 = 0, p11 = 0;
        const ulonglong2* H0 = (const ulonglong2*)&hbuf[cur][0][0];
        const ulonglong2* H1 = (const ulonglong2*)&hbuf[cur][1][0];
        #pragma unroll
        for (int i = 0; i < 32; i++) {
            ulonglong2 a = H0[i];
            ulonglong2 b = H1[i];
            p00 = ffma2(w2[2 * i],     a.x, p00);
            p01 = ffma2(w2[2 * i + 1], a.y, p01);
            p10 = ffma2(w2[2 * i],     b.x, p10);
            p11 = ffma2(w2[2 * i + 1], b.y, p11);
        }
        float2 u0 = unpk64(p00), u1 = unpk64(p01);
        float2 u2 = unpk64(p10), u3 = unpk64(p11);
        float acc0 = xc0 + (u0.x + u0.y) + (u1.x + u1.y);
        float acc1 = xc1 + (u2.x + u2.y) + (u3.x + u3.y);
        if (s + 1 < S_STEPS) {   // prefetch next step's preactivations
            const float* pn = pbase + (size_t)(s + 1) * sstride;
            xc0 = __ldg(pn);
            xc1 = __ldg(pn + 512);
        }
        gbuf[0][l] = acc0;
        gbuf[1][l] = acc1;
        __syncthreads();
        if (l < 128) {
            const int bb = l >> 6, j = l & 63;
            float gi = gbuf[bb][j];
            float gf = gbuf[bb][64 + j];
            float gg = gbuf[bb][128 + j];
            float go = gbuf[bb][192 + j];
            float cc = cbuf[bb][j];
            float c2 = fsig(gf) * cc + fsig(gi) * ftanh_(gg);
            float h2 = fsig(go) * ftanh_(c2);
            cbuf[bb][j] = c2;
            const int hj = r * 64 + j;
            hbuf[nxt][bb][hj] = h2;
            st_cluster_f32(h_remote + (uint32_t)(((nxt * 2 + bb) * 128 + hj) * 4), h2);
            // release: make the remote h store visible, then signal peer's barrier
            asm volatile("mbarrier.arrive.release.cluster.shared::cluster.b64 _, [%0];"
                         :: "r"(mb_remote) : "memory");
            if (is_time) {
                g_tout[(((size_t)s) * 64 + b0 + bb) * 256 + d * 128 + hj] = h2;
            } else if (s == S_STEPS - 1) {
                g_pout[(size_t)(b0 + bb) * 256 + d * 128 + hj] = h2;
            }
        }
        __syncthreads();   // local hbuf[nxt]/cbuf visible; gbuf reusable
        // wait for peer's 128 arrivals for this step (acquire, cluster scope)
        {
            const uint32_t par = (uint32_t)(s & 1);
            asm volatile(
                "{\n\t"
                ".reg .pred P;\n\t"
                "WL%=:\n\t"
                "mbarrier.try_wait.parity.acquire.cluster.shared::cta.b64 P, [%0], %1, 0x989680;\n\t"
                "@P bra WD%=;\n\t"
                "bra WL%=;\n\t"
                "WD%=:\n\t"
                "}" :: "r"(mb_local), "r"(par) : "memory");
        }
    }
}

// ---------------- output GEMM ----------------
__global__ void __launch_bounds__(128)
out_gemm_kernel(const float* __restrict__ Wo, const float* __restrict__ bo,
                float* __restrict__ out)
{
    __shared__ float po[256];
    const int b = blockIdx.x, tid = threadIdx.x;
    po[tid]       = g_pout[b * 256 + tid];
    po[tid + 128] = g_pout[b * 256 + 128 + tid];
    __syncthreads();
    if (tid < NO) {
        float acc = bo[tid];
        const float* wr = Wo + tid * 256;
        #pragma unroll 8
        for (int k = 0; k < 256; k += 4) {
            float4 v = *(const float4*)(wr + k);
            acc = fmaf(v.x, po[k],     acc);
            acc = fmaf(v.y, po[k + 1], acc);
            acc = fmaf(v.z, po[k + 2], acc);
            acc = fmaf(v.w, po[k + 3], acc);
        }
        out[b * NO + tid] = acc;
    }
}

// ---------------- launch ----------------
extern "C" void kernel_launch(void* const* d_in, const int* in_sizes, int n_in,
                              void* d_out, int out_size)
{
    const float* x     = (const float*)d_in[0];
    const float* Wt_ih = (const float*)d_in[1];
    const float* Wt_hh = (const float*)d_in[2];
    const float* bt_ih = (const float*)d_in[3];
    const float* bt_hh = (const float*)d_in[4];
    const float* Wp_ih = (const float*)d_in[5];
    const float* Wp_hh = (const float*)d_in[6];
    const float* bp_ih = (const float*)d_in[7];
    const float* bp_hh = (const float*)d_in[8];
    const float* Wo    = (const float*)d_in[9];
    const float* bo    = (const float*)d_in[10];
    float* out = (float*)d_out;

    dim3 ggrid(8, 1024);               // N/128 x M/128
    const int convBlocks = MTOT * 256 / 8 / 256;   // 16384

    // time phase
    conv_a_kernel<<<convBlocks, 256>>>(x, 524288LL, 256LL, 0);
    conv_w_kernel<<<128, 256>>>(Wt_ih, bt_ih, bt_hh);
    mma_gemm_kernel<<<ggrid, 256>>>();
    recur_kernel<<<128, 256>>>(Wt_hh, 1);
    // pitch phase
    conv_a_kernel<<<convBlocks, 256>>>(nullptr, 256LL, 16384LL, 1);
    conv_w_kernel<<<128, 256>>>(Wp_ih, bp_ih, bp_hh);
    mma_gemm_kernel<<<ggrid, 256>>>();
    recur_kernel<<<128, 256>>>(Wp_hh, 0);
    // final projection
    out_gemm_kernel<<<64, 128>>>(Wo, bo, out);
}

// round 12
// speedup vs baseline: 1.5201x; 1.5201x over previous
#include <cuda_runtime.h>
#include <cuda_bf16.h>
#include <cstdint>
#include <math.h>

// Problem constants
#define S_STEPS 2048   // T*P
#define NB      64     // batch
#define NI      256    // input
#define NH      128    // hidden
#define NG      512    // 4*H
#define NO      88     // output
#define MTOT    (S_STEPS * NB)   // 131072 GEMM rows

// Scratch (static __device__ — allocation APIs are forbidden)
__device__ float g_proj[(size_t)2 * S_STEPS * NB * NG];          // 512 MB
__device__ float g_tout[(size_t)S_STEPS * NB * 256];             // 128 MB
__device__ float g_pout[NB * 256];
__device__ __nv_bfloat16 g_Ah[(size_t)MTOT * 256];               // 64 MB
__device__ __nv_bfloat16 g_Al[(size_t)MTOT * 256];               // 64 MB
__device__ __nv_bfloat16 g_Bh[1024 * 256];
__device__ __nv_bfloat16 g_Bl[1024 * 256];
__device__ float g_bias[1024];

// ---------------- helpers ----------------
__device__ __forceinline__ uint32_t smem_u32(const void* p) {
    uint32_t a;
    asm("{ .reg .u64 t; cvta.to.shared.u64 t, %1; cvt.u32.u64 %0, t; }" : "=r"(a) : "l"(p));
    return a;
}
__device__ __forceinline__ uint32_t mapa_rank(uint32_t a, uint32_t rk) {
    uint32_t r;
    asm("mapa.shared::cluster.u32 %0, %1, %2;" : "=r"(r) : "r"(a), "r"(rk));
    return r;
}
__device__ __forceinline__ void st_cluster_f32(uint32_t a, float v) {
    asm volatile("st.shared::cluster.f32 [%0], %1;" :: "r"(a), "f"(v) : "memory");
}
__device__ __forceinline__ void cluster_sync_() {
    asm volatile("barrier.cluster.arrive.aligned;" ::: "memory");
    asm volatile("barrier.cluster.wait.aligned;" ::: "memory");
}
__device__ __forceinline__ float fsig(float x) {
    float e, r;
    asm("ex2.approx.ftz.f32 %0, %1;" : "=f"(e) : "f"(-1.4426950408889634f * x));
    asm("rcp.approx.ftz.f32 %0, %1;" : "=f"(r) : "f"(1.0f + e));
    return r;
}
__device__ __forceinline__ float ftanh_(float x) {
    float e, r;
    asm("ex2.approx.ftz.f32 %0, %1;" : "=f"(e) : "f"(2.8853900817779268f * x));
    asm("rcp.approx.ftz.f32 %0, %1;" : "=f"(r) : "f"(1.0f + e));
    return fmaf(-2.0f, r, 1.0f);   // tanh(x) = 1 - 2/(1+e^{2x})
}
__device__ __forceinline__ void mma16816(float* c, const uint32_t* a, const uint32_t* b) {
    asm volatile(
        "mma.sync.aligned.m16n8k16.row.col.f32.bf16.bf16.f32 "
        "{%0,%1,%2,%3}, {%4,%5,%6,%7}, {%8,%9}, {%0,%1,%2,%3};"
        : "+f"(c[0]), "+f"(c[1]), "+f"(c[2]), "+f"(c[3])
        : "r"(a[0]), "r"(a[1]), "r"(a[2]), "r"(a[3]), "r"(b[0]), "r"(b[1]));
}

// ---------------- conversion: fp32 A (strided) -> bf16 hi/lo [m][k] ----------------
__global__ void __launch_bounds__(256)
conv_a_kernel(const float* __restrict__ Aext, long long sbB, long long sbS, int internal)
{
    const float* A = internal ? (const float*)g_tout : Aext;
    size_t idx = ((size_t)blockIdx.x * 256 + threadIdx.x) * 8;
    int m = (int)(idx >> 8), k = (int)(idx & 255);
    const float* src = A + (size_t)(m & 63) * sbB + (size_t)(m >> 6) * sbS + k;
    float4 v0 = *(const float4*)src;
    float4 v1 = *(const float4*)(src + 4);
    float f[8] = {v0.x, v0.y, v0.z, v0.w, v1.x, v1.y, v1.z, v1.w};
    union { __nv_bfloat16 b[8]; uint4 u; } hi, lo;
    #pragma unroll
    for (int i = 0; i < 8; i++) {
        hi.b[i] = __float2bfloat16(f[i]);
        lo.b[i] = __float2bfloat16(f[i] - __bfloat162float(hi.b[i]));
    }
    *(uint4*)&g_Ah[idx] = hi.u;
    *(uint4*)&g_Al[idx] = lo.u;
}

// ---------------- conversion: W -> permuted bf16 hi/lo + fused bias ----------------
__global__ void __launch_bounds__(256)
conv_w_kernel(const float* __restrict__ W, const float* __restrict__ bia,
              const float* __restrict__ bib)
{
    size_t idx = ((size_t)blockIdx.x * 256 + threadIdx.x) * 8;
    int n = (int)(idx >> 8), k = (int)(idx & 255);
    int p = n & 511, d = n >> 9;
    int orig = ((p >> 6) & 3) * 128 + ((p >> 8) & 1) * 64 + (p & 63);
    int row = d * 512 + orig;
    const float* src = W + (size_t)row * 256 + k;
    float4 v0 = *(const float4*)src;
    float4 v1 = *(const float4*)(src + 4);
    float f[8] = {v0.x, v0.y, v0.z, v0.w, v1.x, v1.y, v1.z, v1.w};
    union { __nv_bfloat16 b[8]; uint4 u; } hi, lo;
    #pragma unroll
    for (int i = 0; i < 8; i++) {
        hi.b[i] = __float2bfloat16(f[i]);
        lo.b[i] = __float2bfloat16(f[i] - __bfloat162float(hi.b[i]));
    }
    *(uint4*)&g_Bh[idx] = hi.u;
    *(uint4*)&g_Bl[idx] = lo.u;
    if (k == 0) g_bias[n] = bia[row] + bib[row];
}

// ---------------- tensor-core projection GEMM (split-bf16, 3 terms) ----------------
// C[m][n] = sum_k A[m][k]*B[n][k] + bias[n]; out to g_proj[d][s][b][p] (p permuted).
// CTA tile 128x128, K-chunk 32, 8 warps as 4(m) x 2(n), warp tile 32x64.
__global__ void __launch_bounds__(256)
mma_gemm_kernel()
{
    __shared__ __align__(16) __nv_bfloat16 sm[4][128][40];  // Ah, Al, Bh, Bl; stride 40 halves

    const int tid = threadIdx.x;
    const int m0 = blockIdx.y * 128;
    const int n0 = blockIdx.x * 128;
    const int d  = blockIdx.x >> 2;

    const int lane = tid & 31, wid = tid >> 5;
    const int wm = wid >> 1, wn = wid & 1;
    const int fr = lane >> 2, fq = lane & 3;

    float c[2][8][4];
    #pragma unroll
    for (int i = 0; i < 2; i++)
        #pragma unroll
        for (int j = 0; j < 8; j++)
            #pragma unroll
            for (int q = 0; q < 4; q++) c[i][j][q] = 0.0f;

    // gmem load assignment: thread -> (row, 16-element half of the 32-wide chunk)
    // Each thread loads/stores TWO uint4 (16 bf16) per buffer. 256 thr * 16 = 4096 = full tile.
    const int lrow = tid >> 1, lpart = (tid & 1) * 16;
    const __nv_bfloat16* pAh = g_Ah + (size_t)(m0 + lrow) * 256 + lpart;
    const __nv_bfloat16* pAl = g_Al + (size_t)(m0 + lrow) * 256 + lpart;
    const __nv_bfloat16* pBh = g_Bh + (size_t)(n0 + lrow) * 256 + lpart;
    const __nv_bfloat16* pBl = g_Bl + (size_t)(n0 + lrow) * 256 + lpart;

    uint4 ra0 = *(const uint4*)pAh, ra1 = *(const uint4*)(pAh + 8);
    uint4 rb0 = *(const uint4*)pAl, rb1 = *(const uint4*)(pAl + 8);
    uint4 rc0 = *(const uint4*)pBh, rc1 = *(const uint4*)(pBh + 8);
    uint4 rd0 = *(const uint4*)pBl, rd1 = *(const uint4*)(pBl + 8);

    for (int ch = 0; ch < 8; ch++) {
        *(uint4*)&sm[0][lrow][lpart]     = ra0;
        *(uint4*)&sm[0][lrow][lpart + 8] = ra1;
        *(uint4*)&sm[1][lrow][lpart]     = rb0;
        *(uint4*)&sm[1][lrow][lpart + 8] = rb1;
        *(uint4*)&sm[2][lrow][lpart]     = rc0;
        *(uint4*)&sm[2][lrow][lpart + 8] = rc1;
        *(uint4*)&sm[3][lrow][lpart]     = rd0;
        *(uint4*)&sm[3][lrow][lpart + 8] = rd1;
        __syncthreads();
        if (ch < 7) {
            pAh += 32; pAl += 32; pBh += 32; pBl += 32;
            ra0 = *(const uint4*)pAh; ra1 = *(const uint4*)(pAh + 8);
            rb0 = *(const uint4*)pAl; rb1 = *(const uint4*)(pAl + 8);
            rc0 = *(const uint4*)pBh; rc1 = *(const uint4*)(pBh + 8);
            rd0 = *(const uint4*)pBl; rd1 = *(const uint4*)(pBl + 8);
        }
        #pragma unroll
        for (int ks = 0; ks < 32; ks += 16) {
            uint32_t ah[2][4], al[2][4];
            #pragma unroll
            for (int mt = 0; mt < 2; mt++) {
                int rbase = wm * 32 + mt * 16;
                int col = ks + fq * 2;
                ah[mt][0] = *(const uint32_t*)&sm[0][rbase + fr][col];
                ah[mt][1] = *(const uint32_t*)&sm[0][rbase + 8 + fr][col];
                ah[mt][2] = *(const uint32_t*)&sm[0][rbase + fr][col + 8];
                ah[mt][3] = *(const uint32_t*)&sm[0][rbase + 8 + fr][col + 8];
                al[mt][0] = *(const uint32_t*)&sm[1][rbase + fr][col];
                al[mt][1] = *(const uint32_t*)&sm[1][rbase + 8 + fr][col];
                al[mt][2] = *(const uint32_t*)&sm[1][rbase + fr][col + 8];
                al[mt][3] = *(const uint32_t*)&sm[1][rbase + 8 + fr][col + 8];
            }
            #pragma unroll
            for (int nt = 0; nt < 8; nt++) {
                int nr = wn * 64 + nt * 8 + fr;
                int col = ks + fq * 2;
                uint32_t bh[2], bl[2];
                bh[0] = *(const uint32_t*)&sm[2][nr][col];
                bh[1] = *(const uint32_t*)&sm[2][nr][col + 8];
                bl[0] = *(const uint32_t*)&sm[3][nr][col];
                bl[1] = *(const uint32_t*)&sm[3][nr][col + 8];
                #pragma unroll
                for (int mt = 0; mt < 2; mt++) {
                    mma16816(c[mt][nt], ah[mt], bh);   // hi*hi
                    mma16816(c[mt][nt], ah[mt], bl);   // hi*lo
                    mma16816(c[mt][nt], al[mt], bh);   // lo*hi
                }
            }
        }
        __syncthreads();
    }

    // epilogue: bias + permuted-layout store to g_proj
    #pragma unroll
    for (int nt = 0; nt < 8; nt++) {
        int n = n0 + wn * 64 + nt * 8 + fq * 2;
        float b0 = g_bias[n], b1 = g_bias[n + 1];
        int pcol = n & 511;
        #pragma unroll
        for (int mt = 0; mt < 2; mt++) {
            int m1 = m0 + wm * 32 + mt * 16 + fr;
            int m2 = m1 + 8;
            size_t o1 = (((size_t)d * S_STEPS + (m1 >> 6)) * 64 + (m1 & 63)) * 512 + pcol;
            size_t o2 = (((size_t)d * S_STEPS + (m2 >> 6)) * 64 + (m2 & 63)) * 512 + pcol;
            float2 w1 = make_float2(c[mt][nt][0] + b0, c[mt][nt][1] + b1);
            float2 w2 = make_float2(c[mt][nt][2] + b0, c[mt][nt][3] + b1);
            *(float2*)(g_proj + o1) = w1;
            *(float2*)(g_proj + o2) = w2;
        }
    }
}

// ---------------- recurrent scan (warp-local shfl reduction, no mid-step sync) ----------------
// 128 blocks: (dir d, batch-pair bg, half r). Cluster of 2 = the two halves.
// Thread (j = l>>2, q = l&3): all 4 gates of unit r*64+j, k-quarter [32q, 32q+32).
// Gate sums reduced across q lanes via shfl.bfly; c-state lives in a register.
// h halves exchanged via DSMEM; one barrier.cluster per step (proven round-3/9 protocol).
// hbuf layout: 4 quarters padded to 36 floats each -> q-groups hit disjoint bank groups.
__global__ void __launch_bounds__(256, 1) __cluster_dims__(2, 1, 1)
recur_kernel(const float* __restrict__ Whh, int is_time)
{
    __shared__ __align__(16) float hbuf[2][2][144];  // [ping][batch][4*36]

    const int blk  = blockIdx.x;
    const int r    = blk & 1;
    const int pair = blk >> 1;
    const int d    = pair >> 5;
    const int bg   = pair & 31;
    const int l    = threadIdx.x;
    const int j    = l >> 2;      // unit 0..63
    const int q    = l & 3;       // k-quarter

    // weights: 4 gate rows (t*128 + r*64 + j), k in [32q, 32q+32) -> 128 regs
    float w[4][32];
    #pragma unroll
    for (int t = 0; t < 4; t++) {
        const float* wr = Whh + ((size_t)d * 512 + t * 128 + r * 64 + j) * 128 + q * 32;
        #pragma unroll
        for (int kk = 0; kk < 32; kk += 4) {
            float4 v = *(const float4*)(wr + kk);
            w[t][kk] = v.x; w[t][kk + 1] = v.y; w[t][kk + 2] = v.z; w[t][kk + 3] = v.w;
        }
    }

    if (l < 144) {
        hbuf[0][0][l] = 0.f; hbuf[0][1][l] = 0.f;
        hbuf[1][0][l] = 0.f; hbuf[1][1][l] = 0.f;
    }
    __syncthreads();
    cluster_sync_();   // peer's remote writes must not race our init

    const int b0 = bg * 2;
    // preactivations for this thread's unit: permuted index p = r*256 + t*64 + j, batch b0+(q&1)
    const size_t xstride = (size_t)64 * 512;
    const float* xbase = g_proj + (((size_t)d * S_STEPS) * 64 + (b0 + (q & 1))) * 512
                         + r * 256 + j;
    float xc[4];
    #pragma unroll
    for (int t = 0; t < 4; t++) xc[t] = __ldg(xbase + t * 64);
    float cst = 0.f;   // cell state for (unit j, batch b0+q), valid on q<2

    const uint32_t h_local  = smem_u32(&hbuf[0][0][0]);
    const uint32_t h_remote = mapa_rank(h_local, (uint32_t)(r ^ 1));

    for (int s = 0; s < S_STEPS; ++s) {
        const int cur = s & 1, nxt = cur ^ 1;
        float acc[4][2];
        #pragma unroll
        for (int t = 0; t < 4; t++) { acc[t][0] = 0.f; acc[t][1] = 0.f; }

        const float4* h0 = (const float4*)&hbuf[cur][0][q * 36];
        const float4* h1 = (const float4*)&hbuf[cur][1][q * 36];
        #pragma unroll
        for (int k4 = 0; k4 < 8; k4++) {
            float4 a = h0[k4];
            float4 b = h1[k4];
            #pragma unroll
            for (int t = 0; t < 4; t++) {
                acc[t][0] = fmaf(w[t][k4 * 4 + 0], a.x, acc[t][0]);
                acc[t][0] = fmaf(w[t][k4 * 4 + 1], a.y, acc[t][0]);
                acc[t][0] = fmaf(w[t][k4 * 4 + 2], a.z, acc[t][0]);
                acc[t][0] = fmaf(w[t][k4 * 4 + 3], a.w, acc[t][0]);
                acc[t][1] = fmaf(w[t][k4 * 4 + 0], b.x, acc[t][1]);
                acc[t][1] = fmaf(w[t][k4 * 4 + 1], b.y, acc[t][1]);
                acc[t][1] = fmaf(w[t][k4 * 4 + 2], b.z, acc[t][1]);
                acc[t][1] = fmaf(w[t][k4 * 4 + 3], b.w, acc[t][1]);
            }
        }

        // prefetch next step's preactivations (hidden under reduction + epilogue)
        float xn[4] = {0.f, 0.f, 0.f, 0.f};
        if (q < 2 && s + 1 < S_STEPS) {
            const float* pn = xbase + (size_t)(s + 1) * xstride;
            #pragma unroll
            for (int t = 0; t < 4; t++) xn[t] = __ldg(pn + t * 64);
        }

        // reduce partial dots across the 4 q-lanes (lane bits 0-1)
        #pragma unroll
        for (int t = 0; t < 4; t++) {
            #pragma unroll
            for (int bb = 0; bb < 2; bb++) {
                acc[t][bb] += __shfl_xor_sync(0xffffffffu, acc[t][bb], 1);
                acc[t][bb] += __shfl_xor_sync(0xffffffffu, acc[t][bb], 2);
            }
        }

        if (q < 2) {
            float gi = acc[0][q] + xc[0];
            float gf = acc[1][q] + xc[1];
            float gg = acc[2][q] + xc[2];
            float go = acc[3][q] + xc[3];
            float c2 = fsig(gf) * cst + fsig(gi) * ftanh_(gg);
            float h2 = fsig(go) * ftanh_(c2);
            cst = c2;
            const int hj = r * 64 + j;
            const int hoff = (hj >> 5) * 36 + (hj & 31);
            hbuf[nxt][q][hoff] = h2;
            st_cluster_f32(h_remote + (uint32_t)(((nxt * 2 + q) * 144 + hoff) * 4), h2);
            if (is_time) {
                g_tout[(((size_t)s) * 64 + b0 + q) * 256 + d * 128 + hj] = h2;
            } else if (s == S_STEPS - 1) {
                g_pout[(size_t)(b0 + q) * 256 + d * 128 + hj] = h2;
            }
            xc[0] = xn[0]; xc[1] = xn[1]; xc[2] = xn[2]; xc[3] = xn[3];
        }
        cluster_sync_();   // release h-half writes (local + remote), acquire peer's
    }
}

// ---------------- output GEMM ----------------
__global__ void __launch_bounds__(128)
out_gemm_kernel(const float* __restrict__ Wo, const float* __restrict__ bo,
                float* __restrict__ out)
{
    __shared__ float po[256];
    const int b = blockIdx.x, tid = threadIdx.x;
    po[tid]       = g_pout[b * 256 + tid];
    po[tid + 128] = g_pout[b * 256 + 128 + tid];
    __syncthreads();
    if (tid < NO) {
        float acc = bo[tid];
        const float* wr = Wo + tid * 256;
        #pragma unroll 8
        for (int k = 0; k < 256; k += 4) {
            float4 v = *(const float4*)(wr + k);
            acc = fmaf(v.x, po[k],     acc);
            acc = fmaf(v.y, po[k + 1], acc);
            acc = fmaf(v.z, po[k + 2], acc);
            acc = fmaf(v.w, po[k + 3], acc);
        }
        out[b * NO + tid] = acc;
    }
}

// ---------------- launch ----------------
extern "C" void kernel_launch(void* const* d_in, const int* in_sizes, int n_in,
                              void* d_out, int out_size)
{
    const float* x     = (const float*)d_in[0];
    const float* Wt_ih = (const float*)d_in[1];
    const float* Wt_hh = (const float*)d_in[2];
    const float* bt_ih = (const float*)d_in[3];
    const float* bt_hh = (const float*)d_in[4];
    const float* Wp_ih = (const float*)d_in[5];
    const float* Wp_hh = (const float*)d_in[6];
    const float* bp_ih = (const float*)d_in[7];
    const float* bp_hh = (const float*)d_in[8];
    const float* Wo    = (const float*)d_in[9];
    const float* bo    = (const float*)d_in[10];
    float* out = (float*)d_out;

    dim3 ggrid(8, 1024);               // N/128 x M/128
    const int convBlocks = MTOT * 256 / 8 / 256;   // 16384

    // time phase
    conv_a_kernel<<<convBlocks, 256>>>(x, 524288LL, 256LL, 0);
    conv_w_kernel<<<128, 256>>>(Wt_ih, bt_ih, bt_hh);
    mma_gemm_kernel<<<ggrid, 256>>>();
    recur_kernel<<<128, 256>>>(Wt_hh, 1);
    // pitch phase
    conv_a_kernel<<<convBlocks, 256>>>(nullptr, 256LL, 16384LL, 1);
    conv_w_kernel<<<128, 256>>>(Wp_ih, bp_ih, bp_hh);
    mma_gemm_kernel<<<ggrid, 256>>>();
    recur_kernel<<<128, 256>>>(Wp_hh, 0);
    // final projection
    out_gemm_kernel<<<64, 128>>>(Wo, bo, out);
}